// round 2
// baseline (speedup 1.0000x reference)
#include <cuda_runtime.h>

#define HH 256
#define WW 256
#define PP 512
// ALPHA = -5.0f, 1/ALPHA = -0.2f

__device__ float g_partB[PP * HH];   // transposed: [point][row], 512KB
__device__ float g_numA[HH];
__device__ float g_denA[HH];

__device__ __forceinline__ float frcp_a(float x) {
    float r; asm("rcp.approx.f32 %0, %1;" : "=f"(r) : "f"(x)); return r;
}
__device__ __forceinline__ float frsqrt_a(float x) {
    float r; asm("rsqrt.approx.f32 %0, %1;" : "=f"(r) : "f"(x)); return r;
}

// ---------------------------------------------------------------------------
// Fused kernel: one block per row (256 blocks x 256 threads).
//  - local corner-max over points  -> M (global max dist, separable argument)
//  - phase A: per-pixel min dist   -> term-1 row partials
//  - phase B: soft-min power sums  -> per-(point,row) partials (transposed)
// ---------------------------------------------------------------------------
__global__ __launch_bounds__(256) void k_main(const float* __restrict__ hm,
                                              const float* __restrict__ pts) {
    __shared__ float2 pre[PP];     // (px, dx*dx) per point for this row
    __shared__ float  s_hm[WW];
    __shared__ float  s_red[8], s_red2[8];
    __shared__ float  s_M;

    int tid = threadIdx.x;
    int y   = blockIdx.x;
    float yf = (float)y;

    // Load points, build per-row table, and fold in the corner-max:
    // max over grid of (y-py)^2+(x-px)^2 is separable -> attained at corners.
    float lmax = 0.f;
    for (int j = tid; j < PP; j += 256) {
        float py = pts[2 * j], px = pts[2 * j + 1];
        float dx = yf - py;
        pre[j] = make_float2(px, dx * dx);
        float my = fmaxf(py, 255.0f - py);
        float mx = fmaxf(px, 255.0f - px);
        lmax = fmaxf(lmax, fmaf(my, my, mx * mx));
    }
    s_hm[tid] = hm[y * WW + tid];

    int warp = tid >> 5, lane = tid & 31;
    for (int o = 16; o > 0; o >>= 1)
        lmax = fmaxf(lmax, __shfl_down_sync(0xffffffffu, lmax, o));
    if (lane == 0) s_red[warp] = lmax;
    __syncthreads();
    if (tid == 0) {
        float m = s_red[0];
#pragma unroll
        for (int i = 1; i < 8; ++i) m = fmaxf(m, s_red[i]);
        s_M = sqrtf(m);
    }
    __syncthreads();
    float M = s_M;

    // ---------------- Phase A: min squared distance per pixel ----------------
    float xf = (float)tid;
    float mins = 3.4e38f;
    const float4* p4 = reinterpret_cast<const float4*>(pre);
#pragma unroll 8
    for (int k = 0; k < PP / 2; ++k) {
        float4 q = p4[k];                 // two points per LDS.128 (broadcast)
        float a = xf - q.x; float s0 = fmaf(a, a, q.y);
        float b = xf - q.z; float s1 = fmaf(b, b, q.w);
        mins = fminf(mins, fminf(s0, s1));
    }
    float h  = s_hm[tid];
    float t1 = h * sqrtf(mins);
    float ah = fabsf(h);
    for (int o = 16; o > 0; o >>= 1) {
        t1 += __shfl_down_sync(0xffffffffu, t1, o);
        ah += __shfl_down_sync(0xffffffffu, ah, o);
    }
    if (lane == 0) { s_red[warp] = t1; s_red2[warp] = ah; }
    __syncthreads();
    if (tid == 0) {
        float a = 0.f, b = 0.f;
#pragma unroll
        for (int i = 0; i < 8; ++i) { a += s_red[i]; b += s_red2[i]; }
        g_numA[y] = a;
        g_denA[y] = b;
    }

    // ---------------- Phase B: soft-min power sums (2 points/thread) ---------
    float2 pA = pre[tid], pB = pre[tid + 256];
    float dxsA = pA.y, dxsB = pB.y;
    float dyA = -1.0f - pA.x;             // +1 at loop head -> dy(x=0) = -px
    float dyB = -1.0f - pB.x;
    float SA = 0.f, SB = 0.f;

#pragma unroll 4
    for (int x = 0; x < WW; ++x) {
        float h2 = s_hm[x];
        float bb = fmaf(-h2, M, M);       // (1-h)*M
        dyA += 1.0f;
        dyB += 1.0f;
        float sA = fmaf(dyA, dyA, dxsA);
        float sB = fmaf(dyB, dyB, dxsB);
        float rA = frsqrt_a(sA);
        float rB = frsqrt_a(sB);
        float dA = sA * rA;               // sqrt(s)
        float dB = sB * rB;
        float wA = fmaf(h2, dA, bb);
        float wB = fmaf(h2, dB, bb);
        float qA = frcp_a(wA);
        float qB = frcp_a(wB);
        float qA2 = qA * qA, qB2 = qB * qB;
        float qA4 = qA2 * qA2, qB4 = qB2 * qB2;
        SA = fmaf(qA4, qA, SA);           // += w^-5
        SB = fmaf(qB4, qB, SB);
    }
    g_partB[tid * HH + y]         = SA;   // transposed for coalesced finalize
    g_partB[(tid + 256) * HH + y] = SB;
}

// ---------------------------------------------------------------------------
// Finalize: per-point contiguous float4 sums (high MLP), powf, deterministic
// tree reductions, combine.
// ---------------------------------------------------------------------------
__global__ __launch_bounds__(512) void k_final(float* __restrict__ out) {
    int j = threadIdx.x;                  // 512 threads = 512 points
    const float4* p = reinterpret_cast<const float4*>(g_partB) + j * (HH / 4);
    float S = 0.f;
#pragma unroll 8
    for (int i = 0; i < HH / 4; ++i) {
        float4 v = p[i];
        S += (v.x + v.y) + (v.z + v.w);
    }
    float smv = powf(S * (1.0f / (HH * WW)), -0.2f);   // mean^(1/ALPHA)

    __shared__ float red[PP];
    red[j] = smv;
    __syncthreads();
    for (int o = 256; o > 0; o >>= 1) {
        if (j < o) red[j] += red[j + o];
        __syncthreads();
    }

    __shared__ float r2[HH], r3[HH];
    if (j < HH) { r2[j] = g_numA[j]; r3[j] = g_denA[j]; }
    __syncthreads();
    for (int o = 128; o > 0; o >>= 1) {
        if (j < o) { r2[j] += r2[j + o]; r3[j] += r3[j + o]; }
        __syncthreads();
    }

    if (j == 0) {
        out[0] = r2[0] / r3[0] + red[0] * (1.0f / PP);
    }
}

extern "C" void kernel_launch(void* const* d_in, const int* in_sizes, int n_in,
                              void* d_out, int out_size) {
    (void)in_sizes; (void)n_in; (void)out_size;
    const float* hm  = (const float*)d_in[0];   // heat_map (256*256)
    const float* pts = (const float*)d_in[1];   // points   (512*2)
    float* out = (float*)d_out;

    k_main<<<HH, 256>>>(hm, pts);
    k_final<<<1, 512>>>(out);
}

// round 3
// speedup vs baseline: 1.3107x; 1.3107x over previous
#include <cuda_runtime.h>

#define HH 256
#define WW 256
#define PP 512
// ALPHA = -5.0f, 1/ALPHA = -0.2f

__device__ float g_partB[HH * PP];   // [row][point] — coalesced writes AND reads
__device__ float g_numA[HH];
__device__ float g_denA[HH];
__device__ float g_smv[PP];

__device__ __forceinline__ float frcp_a(float x) {
    float r; asm("rcp.approx.f32 %0, %1;" : "=f"(r) : "f"(x)); return r;
}
__device__ __forceinline__ float frsqrt_a(float x) {
    float r; asm("rsqrt.approx.f32 %0, %1;" : "=f"(r) : "f"(x)); return r;
}

// ---------------------------------------------------------------------------
// Fused main kernel: one block per row (256 blocks x 256 threads).
//  - local corner-max over points  -> M (global max dist; argument separable)
//  - phase A: per-pixel min dist   -> term-1 row partials
//  - phase B: soft-min power sums  -> per-(row,point) partials (coalesced)
// ---------------------------------------------------------------------------
__global__ __launch_bounds__(256) void k_main(const float* __restrict__ hm,
                                              const float* __restrict__ pts) {
    __shared__ float2 pre[PP];     // (px, dx*dx) per point for this row
    __shared__ float  s_hm[WW];
    __shared__ float  s_red[8], s_red2[8];
    __shared__ float  s_M;

    int tid = threadIdx.x;
    int y   = blockIdx.x;
    float yf = (float)y;

    // Load points, build per-row table, fold in the corner-max (max squared
    // distance over the grid is separable -> attained at a grid corner).
    float lmax = 0.f;
    for (int j = tid; j < PP; j += 256) {
        float py = pts[2 * j], px = pts[2 * j + 1];
        float dx = yf - py;
        pre[j] = make_float2(px, dx * dx);
        float my = fmaxf(py, 255.0f - py);
        float mx = fmaxf(px, 255.0f - px);
        lmax = fmaxf(lmax, fmaf(my, my, mx * mx));
    }
    s_hm[tid] = hm[y * WW + tid];

    int warp = tid >> 5, lane = tid & 31;
    for (int o = 16; o > 0; o >>= 1)
        lmax = fmaxf(lmax, __shfl_down_sync(0xffffffffu, lmax, o));
    if (lane == 0) s_red[warp] = lmax;
    __syncthreads();
    if (tid == 0) {
        float m = s_red[0];
#pragma unroll
        for (int i = 1; i < 8; ++i) m = fmaxf(m, s_red[i]);
        s_M = sqrtf(m);
    }
    __syncthreads();
    float M = s_M;

    // ---------------- Phase A: min squared distance per pixel ----------------
    float xf = (float)tid;
    float mins = 3.4e38f;
    const float4* p4 = reinterpret_cast<const float4*>(pre);
#pragma unroll 8
    for (int k = 0; k < PP / 2; ++k) {
        float4 q = p4[k];                 // two points per LDS.128 (broadcast)
        float a = xf - q.x; float s0 = fmaf(a, a, q.y);
        float b = xf - q.z; float s1 = fmaf(b, b, q.w);
        mins = fminf(mins, fminf(s0, s1));
    }
    float h  = s_hm[tid];
    float t1 = h * sqrtf(mins);
    float ah = fabsf(h);
    for (int o = 16; o > 0; o >>= 1) {
        t1 += __shfl_down_sync(0xffffffffu, t1, o);
        ah += __shfl_down_sync(0xffffffffu, ah, o);
    }
    if (lane == 0) { s_red[warp] = t1; s_red2[warp] = ah; }
    __syncthreads();
    if (tid == 0) {
        float a = 0.f, b = 0.f;
#pragma unroll
        for (int i = 0; i < 8; ++i) { a += s_red[i]; b += s_red2[i]; }
        g_numA[y] = a;
        g_denA[y] = b;
    }

    // ---------------- Phase B: soft-min power sums (2 points/thread) ---------
    float2 pA = pre[tid], pB = pre[tid + 256];
    float dxsA = pA.y, dxsB = pB.y;
    float dyA = -1.0f - pA.x;             // +1 at loop head -> dy(x=0) = -px
    float dyB = -1.0f - pB.x;
    float SA = 0.f, SB = 0.f;

#pragma unroll 4
    for (int x = 0; x < WW; ++x) {
        float h2 = s_hm[x];
        float bb = fmaf(-h2, M, M);       // (1-h)*M
        dyA += 1.0f;
        dyB += 1.0f;
        float sA = fmaf(dyA, dyA, dxsA);
        float sB = fmaf(dyB, dyB, dxsB);
        float rA = frsqrt_a(sA);
        float rB = frsqrt_a(sB);
        float dA = sA * rA;               // sqrt(s)
        float dB = sB * rB;
        float wA = fmaf(h2, dA, bb);
        float wB = fmaf(h2, dB, bb);
        float qA = frcp_a(wA);
        float qB = frcp_a(wB);
        float qA2 = qA * qA, qB2 = qB * qB;
        float qA4 = qA2 * qA2, qB4 = qB2 * qB2;
        SA = fmaf(qA4, qA, SA);           // += w^-5
        SB = fmaf(qB4, qB, SB);
    }
    g_partB[y * PP + tid]       = SA;     // fully coalesced (2KB per block)
    g_partB[y * PP + tid + 256] = SB;
}

// ---------------------------------------------------------------------------
// Reduce over rows: 16 blocks x 256 threads. Block b owns points
// [b*32, b*32+32). Warp g sums rows g, g+8, ..., g+248 — every load is a
// full 128B coalesced line. Then 8-way smem combine + powf per point.
// ---------------------------------------------------------------------------
__global__ __launch_bounds__(256) void k_reduce() {
    __shared__ float s_acc[8][32];
    int lane = threadIdx.x & 31;          // point within tile
    int g    = threadIdx.x >> 5;          // row group (warp)
    int j    = blockIdx.x * 32 + lane;    // global point index

    float S = 0.f;
#pragma unroll 8
    for (int y = g; y < HH; y += 8)
        S += g_partB[y * PP + j];
    s_acc[g][lane] = S;
    __syncthreads();

    if (g == 0) {
        float T = s_acc[0][lane];
#pragma unroll
        for (int i = 1; i < 8; ++i) T += s_acc[i][lane];
        g_smv[j] = powf(T * (1.0f / (HH * WW)), -0.2f);   // mean^(1/ALPHA)
    }
}

// ---------------------------------------------------------------------------
// Final combine: tiny deterministic reductions over 512 + 256 + 256 floats.
// ---------------------------------------------------------------------------
__global__ __launch_bounds__(512) void k_fin(float* __restrict__ out) {
    int j = threadIdx.x;
    __shared__ float red[PP];
    red[j] = g_smv[j];
    __syncthreads();
    for (int o = 256; o > 0; o >>= 1) {
        if (j < o) red[j] += red[j + o];
        __syncthreads();
    }

    __shared__ float r2[HH], r3[HH];
    if (j < HH) { r2[j] = g_numA[j]; r3[j] = g_denA[j]; }
    __syncthreads();
    for (int o = 128; o > 0; o >>= 1) {
        if (j < o) { r2[j] += r2[j + o]; r3[j] += r3[j + o]; }
        __syncthreads();
    }

    if (j == 0) {
        out[0] = r2[0] / r3[0] + red[0] * (1.0f / PP);
    }
}

extern "C" void kernel_launch(void* const* d_in, const int* in_sizes, int n_in,
                              void* d_out, int out_size) {
    (void)in_sizes; (void)n_in; (void)out_size;
    const float* hm  = (const float*)d_in[0];   // heat_map (256*256)
    const float* pts = (const float*)d_in[1];   // points   (512*2)
    float* out = (float*)d_out;

    k_main<<<HH, 256>>>(hm, pts);
    k_reduce<<<16, 256>>>();
    k_fin<<<1, 512>>>(out);
}

// round 4
// speedup vs baseline: 1.3821x; 1.0545x over previous
#include <cuda_runtime.h>

#define HH 256
#define WW 256
#define PP 512
// ALPHA = -5.0f, 1/ALPHA = -0.2f

typedef unsigned long long ull;

__device__ float g_smv[PP];
__device__ float g_numA[HH];
__device__ float g_denA[HH];
__device__ int   g_ctr = 0;

__device__ __forceinline__ float frsqrt_a(float x) {
    float r; asm("rsqrt.approx.f32 %0, %1;" : "=f"(r) : "f"(x)); return r;
}
__device__ __forceinline__ ull pk2(float lo, float hi) {
    ull r; asm("mov.b64 %0, {%1, %2};" : "=l"(r) : "f"(lo), "f"(hi)); return r;
}
__device__ __forceinline__ void upk2(ull v, float& lo, float& hi) {
    asm("mov.b64 {%0, %1}, %2;" : "=f"(lo), "=f"(hi) : "l"(v));
}
__device__ __forceinline__ ull f2add(ull a, ull b) {
    ull r; asm("add.rn.f32x2 %0, %1, %2;" : "=l"(r) : "l"(a), "l"(b)); return r;
}
__device__ __forceinline__ ull f2mul(ull a, ull b) {
    ull r; asm("mul.rn.f32x2 %0, %1, %2;" : "=l"(r) : "l"(a), "l"(b)); return r;
}
__device__ __forceinline__ ull f2fma(ull a, ull b, ull c) {
    ull r; asm("fma.rn.f32x2 %0, %1, %2, %3;" : "=l"(r) : "l"(a), "l"(b), "l"(c)); return r;
}

// ---------------------------------------------------------------------------
// Fused main kernel: one block per row (256 blocks x 256 threads).
//  - corner-max over points (separable) -> M (global max distance)
//  - phase A: per-pixel min dist -> term-1 row partials (packed f32x2)
//  - phase B: soft-min power sums, 2 points/thread packed into f32x2 lanes,
//    rcp replaced by magic-seed + 3 Newton iterations (fma-pipe).
// ---------------------------------------------------------------------------
__global__ __launch_bounds__(256) void k_main(const float* __restrict__ hm,
                                              const float* __restrict__ pts,
                                              float* __restrict__ partB) {
    __shared__ float4 pre4[PP / 2];   // (negpx_e, negpx_o, dxs_e, dxs_o)
    __shared__ float2 s_h2[WW];       // (h, h)
    __shared__ float2 s_bb2[WW];      // (bb, bb), bb = (1-h)*M
    __shared__ float  s_red[8], s_red2[8];
    __shared__ float  s_M;

    float* prefs = (float*)pre4;
    int tid = threadIdx.x;
    int y   = blockIdx.x;
    float yf = (float)y;

    // Build per-row point table + fold corner-max (max over grid separable).
    float lmax = 0.f;
    for (int j = tid; j < PP; j += 256) {
        float py = pts[2 * j], px = pts[2 * j + 1];
        float dx = yf - py;
        int cell = j >> 1, half = j & 1;
        prefs[cell * 4 + half]     = -px;
        prefs[cell * 4 + 2 + half] = dx * dx;
        float my = fmaxf(py, 255.0f - py);
        float mx = fmaxf(px, 255.0f - px);
        lmax = fmaxf(lmax, fmaf(my, my, mx * mx));
    }
    float h = hm[y * WW + tid];
    s_h2[tid] = make_float2(h, h);

    int warp = tid >> 5, lane = tid & 31;
    for (int o = 16; o > 0; o >>= 1)
        lmax = fmaxf(lmax, __shfl_down_sync(0xffffffffu, lmax, o));
    if (lane == 0) s_red[warp] = lmax;
    __syncthreads();
    if (tid == 0) {
        float m = s_red[0];
#pragma unroll
        for (int i = 1; i < 8; ++i) m = fmaxf(m, s_red[i]);
        s_M = sqrtf(m);
    }
    __syncthreads();
    float M = s_M;
    float bb = fmaf(-h, M, M);
    s_bb2[tid] = make_float2(bb, bb);

    // ---------------- Phase A: min squared distance per pixel ----------------
    float xf = (float)tid;
    ull  XF2 = pk2(xf, xf);
    float mins = 3.4e38f;
#pragma unroll 8
    for (int k = 0; k < PP / 2; ++k) {
        float4 q = pre4[k];               // broadcast LDS.128
        ull NPX = pk2(q.x, q.y);
        ull DXS = pk2(q.z, q.w);
        ull DY  = f2add(XF2, NPX);        // x - px (px stored negated)
        ull S   = f2fma(DY, DY, DXS);
        float s0, s1; upk2(S, s0, s1);
        mins = fminf(mins, fminf(s0, s1));
    }
    float t1 = h * sqrtf(mins);
    float ah = fabsf(h);
    for (int o = 16; o > 0; o >>= 1) {
        t1 += __shfl_down_sync(0xffffffffu, t1, o);
        ah += __shfl_down_sync(0xffffffffu, ah, o);
    }
    __syncthreads();                      // reuse s_red safely
    if (lane == 0) { s_red[warp] = t1; s_red2[warp] = ah; }
    __syncthreads();
    if (tid == 0) {
        float a = 0.f, b = 0.f;
#pragma unroll
        for (int i = 0; i < 8; ++i) { a += s_red[i]; b += s_red2[i]; }
        g_numA[y] = a;
        g_denA[y] = b;
    }

    // ---------------- Phase B: packed soft-min power sums --------------------
    int base = (tid >> 1) * 4 + (tid & 1);
    float npA = prefs[base],       dxA = prefs[base + 2];
    float npB = prefs[base + 512], dxB = prefs[base + 514];   // point tid+256

    ull DY   = pk2(npA, npB);             // dy(x=0) = -px
    ull DXS  = pk2(dxA, dxB);
    ull ONE2 = pk2(1.0f, 1.0f);
    ull SACC = 0;                         // (0.0f, 0.0f)

    const ull* hp = (const ull*)s_h2;
    const ull* bp = (const ull*)s_bb2;

#pragma unroll 8
    for (int x = 0; x < WW; ++x) {
        ull H2  = hp[x];                  // LDS.64 broadcast
        ull BB2 = bp[x];
        ull S   = f2fma(DY, DY, DXS);
        float sA, sB; upk2(S, sA, sB);
        float rA = frsqrt_a(sA);
        float rB = frsqrt_a(sB);
        ull R = pk2(rA, rB);
        ull D = f2mul(S, R);              // sqrt(s) = s * rsqrt(s)
        ull W = f2fma(H2, D, BB2);        // w = h*d + (1-h)*M
        // Newton reciprocal: seed via magic constant, 3 quadratic iterations
        float wA, wB; upk2(W, wA, wB);
        unsigned iA = 0x7EF311C3u - __float_as_uint(wA);
        unsigned iB = 0x7EF311C3u - __float_as_uint(wB);
        ull Y  = pk2(__uint_as_float(iA), __uint_as_float(iB));
        ull NW = W ^ 0x8000000080000000ULL;
        ull E;
        E = f2fma(NW, Y, ONE2); Y = f2fma(Y, E, Y);
        E = f2fma(NW, Y, ONE2); Y = f2fma(Y, E, Y);
        E = f2fma(NW, Y, ONE2); Y = f2fma(Y, E, Y);
        ull Q2 = f2mul(Y, Y);
        ull Q4 = f2mul(Q2, Q2);
        SACC = f2fma(Q4, Y, SACC);        // += w^-5
        DY = f2add(DY, ONE2);
    }
    float SA, SB; upk2(SACC, SA, SB);
    partB[y * PP + tid]       = SA;       // coalesced 2KB per block
    partB[y * PP + tid + 256] = SB;
}

// ---------------------------------------------------------------------------
// Reduce + finalize in one kernel. 16 blocks x 256 threads; block b owns
// points [32b, 32b+32): warp g sums rows g, g+8, ... (coalesced 128B lines),
// 8-way smem combine, powf -> g_smv. Last-arriving block (fence + atomic
// counter; deterministic fixed-order sums) does the final combine.
// ---------------------------------------------------------------------------
__global__ __launch_bounds__(256) void k_reduce(const float* __restrict__ partB,
                                                float* __restrict__ out) {
    __shared__ float s_acc[8][32];
    int tid  = threadIdx.x;
    int lane = tid & 31;
    int g    = tid >> 5;
    int j    = blockIdx.x * 32 + lane;

    float S = 0.f;
#pragma unroll 8
    for (int y = g; y < HH; y += 8)
        S += partB[y * PP + j];
    s_acc[g][lane] = S;
    __syncthreads();

    if (g == 0) {
        float T = s_acc[0][lane];
#pragma unroll
        for (int i = 1; i < 8; ++i) T += s_acc[i][lane];
        g_smv[j] = powf(T * (1.0f / (HH * WW)), -0.2f);   // mean^(1/ALPHA)
    }

    // last-block final combine
    __shared__ int s_last;
    __threadfence();
    __syncthreads();
    if (tid == 0) s_last = (atomicAdd(&g_ctr, 1) == 15);
    __syncthreads();
    if (!s_last) return;

    __shared__ float r1[256], r2[256], r3[256];
    r1[tid] = g_smv[tid] + g_smv[tid + 256];
    r2[tid] = g_numA[tid];
    r3[tid] = g_denA[tid];
    __syncthreads();
    for (int o = 128; o > 0; o >>= 1) {
        if (tid < o) {
            r1[tid] += r1[tid + o];
            r2[tid] += r2[tid + o];
            r3[tid] += r3[tid + o];
        }
        __syncthreads();
    }
    if (tid == 0) {
        out[0] = r2[0] / r3[0] + r1[0] * (1.0f / PP);
        g_ctr = 0;                        // self-reset for next launch
    }
}

// scratch for per-(row,point) partials lives in a device global (no allocs)
__device__ float g_partB[HH * PP];

extern "C" void kernel_launch(void* const* d_in, const int* in_sizes, int n_in,
                              void* d_out, int out_size) {
    (void)in_sizes; (void)n_in; (void)out_size;
    const float* hm  = (const float*)d_in[0];   // heat_map (256*256)
    const float* pts = (const float*)d_in[1];   // points   (512*2)
    float* out = (float*)d_out;

    float* partB;
    cudaGetSymbolAddress((void**)&partB, g_partB);

    k_main<<<HH, 256>>>(hm, pts, partB);
    k_reduce<<<16, 256>>>(partB, out);
}

// round 5
// speedup vs baseline: 1.4710x; 1.0643x over previous
#include <cuda_runtime.h>

#define HH 256
#define WW 256
#define PP 512
// ALPHA = -5.0f, 1/ALPHA = -0.2f

typedef unsigned long long ull;

__device__ float g_sum[PP];          // zero-init at load; reset by epilogue
__device__ float g_numA[HH];
__device__ float g_denA[HH];
__device__ int   g_ctr = 0;

__device__ __forceinline__ float frsqrt_a(float x) {
    float r; asm("rsqrt.approx.f32 %0, %1;" : "=f"(r) : "f"(x)); return r;
}
__device__ __forceinline__ ull pk2(float lo, float hi) {
    ull r; asm("mov.b64 %0, {%1, %2};" : "=l"(r) : "f"(lo), "f"(hi)); return r;
}
__device__ __forceinline__ void upk2(ull v, float& lo, float& hi) {
    asm("mov.b64 {%0, %1}, %2;" : "=f"(lo), "=f"(hi) : "l"(v));
}
__device__ __forceinline__ ull f2add(ull a, ull b) {
    ull r; asm("add.rn.f32x2 %0, %1, %2;" : "=l"(r) : "l"(a), "l"(b)); return r;
}
__device__ __forceinline__ ull f2mul(ull a, ull b) {
    ull r; asm("mul.rn.f32x2 %0, %1, %2;" : "=l"(r) : "l"(a), "l"(b)); return r;
}
__device__ __forceinline__ ull f2fma(ull a, ull b, ull c) {
    ull r; asm("fma.rn.f32x2 %0, %1, %2, %3;" : "=l"(r) : "l"(a), "l"(b), "l"(c)); return r;
}

// ---------------------------------------------------------------------------
// Single fused kernel: 128 blocks x 512 threads, ONE wave on 148 SMs.
// Block b handles rows 2b and 2b+1 (thread halves). Phase-B sums go through
// atomicAdd into g_sum; the last block does powf + final combine + reset.
// ---------------------------------------------------------------------------
__global__ __launch_bounds__(512) void k_all(const float* __restrict__ hm,
                                             const float* __restrict__ pts,
                                             float* __restrict__ out) {
    __shared__ float4 pre4[2][PP / 2];   // per-row: (negpx_e, negpx_o, dxs_e, dxs_o)
    __shared__ float2 s_h2[2][WW];       // per-row: (h, h)
    __shared__ float2 s_bb2[2][WW];      // per-row: (bb, bb), bb = (1-h)*M
    __shared__ float  s_red[16], s_red2[16];
    __shared__ float  s_M;

    int tid  = threadIdx.x;              // 0..511
    int half = tid >> 8;                 // which row of the pair
    int t    = tid & 255;                // pixel / point-lane index within row
    int y    = blockIdx.x * 2 + half;

    // ---- build both rows' point tables (one point per thread) + corner max --
    float py = pts[2 * tid], px = pts[2 * tid + 1];
    float y0f = (float)(blockIdx.x * 2);
    float dx0 = y0f - py, dx1 = (y0f + 1.0f) - py;
    int cell = tid >> 1, par = tid & 1;
    float* p0 = (float*)pre4[0];
    float* p1 = (float*)pre4[1];
    p0[cell * 4 + par]     = -px;
    p0[cell * 4 + 2 + par] = dx0 * dx0;
    p1[cell * 4 + par]     = -px;
    p1[cell * 4 + 2 + par] = dx1 * dx1;
    // global max dist: squared distance separable -> attained at grid corner
    float my = fmaxf(py, 255.0f - py);
    float mx = fmaxf(px, 255.0f - px);
    float lmax = fmaf(my, my, mx * mx);

    float h = hm[y * WW + t];
    s_h2[half][t] = make_float2(h, h);

    int warp = tid >> 5, lane = tid & 31;
    for (int o = 16; o > 0; o >>= 1)
        lmax = fmaxf(lmax, __shfl_down_sync(0xffffffffu, lmax, o));
    if (lane == 0) s_red[warp] = lmax;
    __syncthreads();
    if (tid == 0) {
        float m = s_red[0];
#pragma unroll
        for (int i = 1; i < 16; ++i) m = fmaxf(m, s_red[i]);
        s_M = sqrtf(m);
    }
    __syncthreads();
    float M = s_M;
    s_bb2[half][t] = make_float2(fmaf(-h, M, M), fmaf(-h, M, M));

    // ---------------- Phase A: min squared distance per pixel ----------------
    float xf = (float)t;
    ull  XF2 = pk2(xf, xf);
    float mins = 3.4e38f;
    const float4* ptab = pre4[half];
#pragma unroll 8
    for (int k = 0; k < PP / 2; ++k) {
        float4 q = ptab[k];               // LDS.128 broadcast within half-warp row
        ull NPX = pk2(q.x, q.y);
        ull DXS = pk2(q.z, q.w);
        ull DY  = f2add(XF2, NPX);        // x - px (px stored negated)
        ull S   = f2fma(DY, DY, DXS);
        float s0, s1; upk2(S, s0, s1);
        mins = fminf(mins, fminf(s0, s1));
    }
    float t1 = h * sqrtf(mins);
    float ah = fabsf(h);
    for (int o = 16; o > 0; o >>= 1) {
        t1 += __shfl_down_sync(0xffffffffu, t1, o);
        ah += __shfl_down_sync(0xffffffffu, ah, o);
    }
    __syncthreads();
    if (lane == 0) { s_red[warp] = t1; s_red2[warp] = ah; }
    __syncthreads();
    if (t == 0) {                         // one finisher per row half
        int w0 = half * 8;
        float a = 0.f, b = 0.f;
#pragma unroll
        for (int i = 0; i < 8; ++i) { a += s_red[w0 + i]; b += s_red2[w0 + i]; }
        g_numA[y] = a;
        g_denA[y] = b;
    }

    // ---------------- Phase B: packed soft-min power sums --------------------
    const float* prefs = (const float*)pre4[half];
    int base = (t >> 1) * 4 + (t & 1);
    float npA = prefs[base],       dxA = prefs[base + 2];      // point t
    float npB = prefs[base + 512], dxB = prefs[base + 514];    // point t+256

    ull DY   = pk2(npA, npB);             // dy(x=0) = -px
    ull DXS  = pk2(dxA, dxB);
    ull ONE2 = pk2(1.0f, 1.0f);
    ull SACC = 0;

    const ull* hp = (const ull*)s_h2[half];
    const ull* bp = (const ull*)s_bb2[half];

#pragma unroll 8
    for (int x = 0; x < WW; ++x) {
        ull H2  = hp[x];                  // LDS.64 broadcast
        ull BB2 = bp[x];
        ull S   = f2fma(DY, DY, DXS);
        float sA, sB; upk2(S, sA, sB);
        float rA = frsqrt_a(sA);
        float rB = frsqrt_a(sB);
        ull R = pk2(rA, rB);
        ull D = f2mul(S, R);              // sqrt(s) = s * rsqrt(s)
        ull W = f2fma(H2, D, BB2);        // w = h*d + (1-h)*M
        // Newton reciprocal: magic seed + 3 quadratic iterations (fma pipe)
        float wA, wB; upk2(W, wA, wB);
        unsigned iA = 0x7EF311C3u - __float_as_uint(wA);
        unsigned iB = 0x7EF311C3u - __float_as_uint(wB);
        ull Y  = pk2(__uint_as_float(iA), __uint_as_float(iB));
        ull NW = W ^ 0x8000000080000000ULL;
        ull E;
        E = f2fma(NW, Y, ONE2); Y = f2fma(Y, E, Y);
        E = f2fma(NW, Y, ONE2); Y = f2fma(Y, E, Y);
        E = f2fma(NW, Y, ONE2); Y = f2fma(Y, E, Y);
        ull Q2 = f2mul(Y, Y);
        ull Q4 = f2mul(Q2, Q2);
        SACC = f2fma(Q4, Y, SACC);        // += w^-5
        DY = f2add(DY, ONE2);
    }
    float SA, SB; upk2(SACC, SA, SB);
    atomicAdd(&g_sum[t],       SA);
    atomicAdd(&g_sum[t + 256], SB);

    // ---------------- last-block epilogue ------------------------------------
    __shared__ int s_last;
    __threadfence();
    __syncthreads();
    if (tid == 0) s_last = (atomicAdd(&g_ctr, 1) == (int)gridDim.x - 1);
    __syncthreads();
    if (!s_last) return;

    float Ssum = g_sum[tid];
    float smv  = powf(Ssum * (1.0f / (HH * WW)), -0.2f);   // mean^(1/ALPHA)
    g_sum[tid] = 0.f;                    // reset for next replay

    float* red = (float*)pre4;           // reuse smem
    float* r2  = (float*)s_h2;
    float* r3  = (float*)s_bb2;
    red[tid] = smv;
    if (tid < HH) { r2[tid] = g_numA[tid]; r3[tid] = g_denA[tid]; }
    __syncthreads();
    for (int o = 256; o > 0; o >>= 1) {
        if (tid < o) {
            red[tid] += red[tid + o];
            if (tid < (o >> 1) || o <= 128) { }   // keep structure simple below
        }
        __syncthreads();
    }
    // r2/r3 are 256 long: reduce separately (deterministic tree)
    for (int o = 128; o > 0; o >>= 1) {
        if (tid < o) { r2[tid] += r2[tid + o]; r3[tid] += r3[tid + o]; }
        __syncthreads();
    }
    if (tid == 0) {
        out[0] = r2[0] / r3[0] + red[0] * (1.0f / PP);
        g_ctr = 0;                       // reset for next replay
    }
}

extern "C" void kernel_launch(void* const* d_in, const int* in_sizes, int n_in,
                              void* d_out, int out_size) {
    (void)in_sizes; (void)n_in; (void)out_size;
    const float* hm  = (const float*)d_in[0];   // heat_map (256*256)
    const float* pts = (const float*)d_in[1];   // points   (512*2)
    float* out = (float*)d_out;

    k_all<<<HH / 2, 512>>>(hm, pts, out);
}

// round 6
// speedup vs baseline: 1.5511x; 1.0544x over previous
#include <cuda_runtime.h>

#define HH 256
#define WW 256
#define PP 512
// ALPHA = -5.0f, 1/ALPHA = -0.2f

typedef unsigned long long ull;

__device__ float g_sum[PP];          // zero-init at load; reset by epilogue
__device__ float g_numA[HH];
__device__ float g_denA[HH];
__device__ int   g_ctr = 0;

__device__ __forceinline__ float frsqrt_a(float x) {
    float r; asm("rsqrt.approx.f32 %0, %1;" : "=f"(r) : "f"(x)); return r;
}
__device__ __forceinline__ ull pk2(float lo, float hi) {
    ull r; asm("mov.b64 %0, {%1, %2};" : "=l"(r) : "f"(lo), "f"(hi)); return r;
}
__device__ __forceinline__ void upk2(ull v, float& lo, float& hi) {
    asm("mov.b64 {%0, %1}, %2;" : "=f"(lo), "=f"(hi) : "l"(v));
}
__device__ __forceinline__ ull f2add(ull a, ull b) {
    ull r; asm("add.rn.f32x2 %0, %1, %2;" : "=l"(r) : "l"(a), "l"(b)); return r;
}
__device__ __forceinline__ ull f2mul(ull a, ull b) {
    ull r; asm("mul.rn.f32x2 %0, %1, %2;" : "=l"(r) : "l"(a), "l"(b)); return r;
}
__device__ __forceinline__ ull f2fma(ull a, ull b, ull c) {
    ull r; asm("fma.rn.f32x2 %0, %1, %2, %3;" : "=l"(r) : "l"(a), "l"(b), "l"(c)); return r;
}

// ---------------------------------------------------------------------------
// Single fused kernel: 128 blocks x 1024 threads (one wave, 8 warps/SMSP).
// Block b owns rows 2b, 2b+1. Per row: 512 threads = 1 point each; the f32x2
// packing runs over PIXEL PAIRS (x, x+1). Soft sums via atomicAdd into g_sum;
// last block (fence + counter) does powf + final combine + state reset.
// ---------------------------------------------------------------------------
__global__ __launch_bounds__(1024) void k_all(const float* __restrict__ hm,
                                              const float* __restrict__ pts,
                                              float* __restrict__ out) {
    __shared__ float2 pre[2][PP];        // per row: (-px, dx*dx) per point
    __shared__ float  s_hm[2][WW];       // per row: h (pixel pairs -> LDS.64)
    __shared__ float  s_min[2][2][WW];   // per row, per point-half: min dist2
    __shared__ float  s_red[32], s_red2[32];
    __shared__ float  s_M;

    int tid  = threadIdx.x;              // 0..1023
    int row  = tid >> 9;                 // 0/1 within the row pair
    int t    = tid & 511;                // point index within row
    int y    = blockIdx.x * 2 + row;

    // ---- build per-row point table + corner max (separable -> grid corner) --
    float py = pts[2 * t], px = pts[2 * t + 1];
    float dx = (float)y - py;
    pre[row][t] = make_float2(-px, dx * dx);
    float my = fmaxf(py, 255.0f - py);
    float mx = fmaxf(px, 255.0f - px);
    float lmax = fmaf(my, my, mx * mx);

    float h = 0.f;
    if (t < WW) {
        h = hm[y * WW + t];
        s_hm[row][t] = h;
    }

    int warp = tid >> 5, lane = tid & 31;
    for (int o = 16; o > 0; o >>= 1)
        lmax = fmaxf(lmax, __shfl_down_sync(0xffffffffu, lmax, o));
    if (lane == 0) s_red[warp] = lmax;
    __syncthreads();
    if (tid == 0) {
        float m = s_red[0];
#pragma unroll
        for (int i = 1; i < 32; ++i) m = fmaxf(m, s_red[i]);
        s_M = sqrtf(m);
    }
    __syncthreads();
    float M = s_M;

    // ---------------- Phase A: per-pixel min dist2 (2 threads/pixel) --------
    {
        int p  = tid & 255;              // pixel
        int hp = (tid >> 8) & 1;         // which half of the points
        float xf = (float)p;
        ull XF2 = pk2(xf, xf);
        const float4* ptab = (const float4*)&pre[row][hp * 256];
        float mins = 3.4e38f;
#pragma unroll 8
        for (int k = 0; k < 128; ++k) {
            float4 q = ptab[k];          // (-px0, dxs0, -px1, dxs1)
            ull NPX = pk2(q.x, q.z);
            ull DXS = pk2(q.y, q.w);
            ull DY  = f2add(XF2, NPX);
            ull S   = f2fma(DY, DY, DXS);
            float s0, s1; upk2(S, s0, s1);
            mins = fminf(mins, fminf(s0, s1));
        }
        s_min[row][hp][p] = mins;
    }
    __syncthreads();
    {
        int p  = tid & 255;
        int hp = (tid >> 8) & 1;
        float t1 = 0.f, ah = 0.f;
        if (hp == 0) {                   // these threads hold h for pixel p
            float mins = fminf(s_min[row][0][p], s_min[row][1][p]);
            t1 = h * sqrtf(mins);
            ah = fabsf(h);
        }
        for (int o = 16; o > 0; o >>= 1) {
            t1 += __shfl_down_sync(0xffffffffu, t1, o);
            ah += __shfl_down_sync(0xffffffffu, ah, o);
        }
        if (lane == 0) { s_red[warp] = t1; s_red2[warp] = ah; }
    }
    __syncthreads();
    if (t == 0) {                        // one finisher per row
        int w0 = row * 16;               // row's hp==0 threads live in warps w0..w0+7
        float a = 0.f, b = 0.f;
#pragma unroll
        for (int i = 0; i < 8; ++i) { a += s_red[w0 + i]; b += s_red2[w0 + i]; }
        g_numA[y] = a;
        g_denA[y] = b;
    }

    // ---------------- Phase B: pixel-pair packed soft-min power sums ---------
    {
        float2 pj = pre[row][t];
        ull DY    = pk2(pj.x, pj.x + 1.0f);   // (x0-px, x1-px) at x=0
        ull DXS   = pk2(pj.y, pj.y);
        ull TWO2  = pk2(2.0f, 2.0f);
        ull ONE2  = pk2(1.0f, 1.0f);
        ull M2    = pk2(M, M);
        ull NM2   = pk2(-M, -M);
        ull SACC  = 0;
        const ull* hp2 = (const ull*)s_hm[row];

#pragma unroll 8
        for (int x = 0; x < WW / 2; ++x) {
            ull H2 = hp2[x];                  // (h[2x], h[2x+1]) LDS.64
            ull S  = f2fma(DY, DY, DXS);
            float sA, sB; upk2(S, sA, sB);
            float rA = frsqrt_a(sA);
            float rB = frsqrt_a(sB);
            ull R  = pk2(rA, rB);
            ull D  = f2mul(S, R);             // sqrt(s)
            ull DM = f2add(D, NM2);           // d - M
            ull W  = f2fma(H2, DM, M2);       // w = h*(d-M) + M
            // Newton reciprocal: magic seed + 2 quadratic iterations
            float wA, wB; upk2(W, wA, wB);
            unsigned iA = 0x7EF311C3u - __float_as_uint(wA);
            unsigned iB = 0x7EF311C3u - __float_as_uint(wB);
            ull Y  = pk2(__uint_as_float(iA), __uint_as_float(iB));
            ull NW = W ^ 0x8000000080000000ULL;
            ull E;
            E = f2fma(NW, Y, ONE2); Y = f2fma(Y, E, Y);
            E = f2fma(NW, Y, ONE2); Y = f2fma(Y, E, Y);
            ull Q2 = f2mul(Y, Y);
            ull Q4 = f2mul(Q2, Q2);
            SACC = f2fma(Q4, Y, SACC);        // += w^-5
            DY = f2add(DY, TWO2);
        }
        float SA, SB; upk2(SACC, SA, SB);
        atomicAdd(&g_sum[t], SA + SB);        // one add per (row, point)
    }

    // ---------------- last-block epilogue ------------------------------------
    __shared__ int s_last;
    __threadfence();
    __syncthreads();
    if (tid == 0) s_last = (atomicAdd(&g_ctr, 1) == (int)gridDim.x - 1);
    __syncthreads();
    if (!s_last) return;

    float* red = (float*)pre;            // reuse smem (>=2KB each)
    float* r2  = (float*)s_hm;
    float* r3  = (float*)s_min;
    if (tid < PP) {
        float Ssum = g_sum[tid];
        red[tid] = powf(Ssum * (1.0f / (HH * WW)), -0.2f);  // mean^(1/ALPHA)
        g_sum[tid] = 0.f;                // reset for next replay
    }
    if (tid < HH) { r2[tid] = g_numA[tid]; r3[tid] = g_denA[tid]; }
    __syncthreads();
    for (int o = 256; o > 0; o >>= 1) {
        if (tid < o) red[tid] += red[tid + o];
        __syncthreads();
    }
    for (int o = 128; o > 0; o >>= 1) {
        if (tid < o) { r2[tid] += r2[tid + o]; r3[tid] += r3[tid + o]; }
        __syncthreads();
    }
    if (tid == 0) {
        out[0] = r2[0] / r3[0] + red[0] * (1.0f / PP);
        g_ctr = 0;                       // reset for next replay
    }
}

extern "C" void kernel_launch(void* const* d_in, const int* in_sizes, int n_in,
                              void* d_out, int out_size) {
    (void)in_sizes; (void)n_in; (void)out_size;
    const float* hm  = (const float*)d_in[0];   // heat_map (256*256)
    const float* pts = (const float*)d_in[1];   // points   (512*2)
    float* out = (float*)d_out;

    k_all<<<HH / 2, 1024>>>(hm, pts, out);
}

// round 7
// speedup vs baseline: 1.5630x; 1.0077x over previous
#include <cuda_runtime.h>

#define HH 256
#define WW 256
#define PP 512
// ALPHA = -5.0f, 1/ALPHA = -0.2f

typedef unsigned long long ull;

__device__ float g_sum[PP];          // zero-init at load; reset by epilogue
__device__ float g_numA[HH];
__device__ float g_denA[HH];
__device__ int   g_ctr = 0;

__device__ __forceinline__ float frsqrt_a(float x) {
    float r; asm("rsqrt.approx.f32 %0, %1;" : "=f"(r) : "f"(x)); return r;
}
__device__ __forceinline__ ull pk2(float lo, float hi) {
    ull r; asm("mov.b64 %0, {%1, %2};" : "=l"(r) : "f"(lo), "f"(hi)); return r;
}
__device__ __forceinline__ void upk2(ull v, float& lo, float& hi) {
    asm("mov.b64 {%0, %1}, %2;" : "=f"(lo), "=f"(hi) : "l"(v));
}
__device__ __forceinline__ ull f2add(ull a, ull b) {
    ull r; asm("add.rn.f32x2 %0, %1, %2;" : "=l"(r) : "l"(a), "l"(b)); return r;
}
__device__ __forceinline__ ull f2mul(ull a, ull b) {
    ull r; asm("mul.rn.f32x2 %0, %1, %2;" : "=l"(r) : "l"(a), "l"(b)); return r;
}
__device__ __forceinline__ ull f2fma(ull a, ull b, ull c) {
    ull r; asm("fma.rn.f32x2 %0, %1, %2, %3;" : "=l"(r) : "l"(a), "l"(b), "l"(c)); return r;
}

// ---------------------------------------------------------------------------
// Single fused kernel: 128 blocks x 1024 threads (one wave, 8 warps/SMSP).
// Block b owns rows 2b, 2b+1 (thread halves; t = point/pixel index in row).
// Quad smem layouts give MOV-free f32x2 operand pairs. Soft sums through
// atomicAdd(g_sum); last block (fence+counter) finalizes and resets state.
// ---------------------------------------------------------------------------
__global__ __launch_bounds__(1024) void k_all(const float* __restrict__ hm,
                                              const float* __restrict__ pts,
                                              float* __restrict__ out) {
    __shared__ float4 pre4[2][PP / 2];   // per row: (-px0,-px1,dxs0,dxs1) quads
    __shared__ float  s_hm[2][WW];       // per row: raw h
    __shared__ float4 s_hb[2][WW / 2];   // per row: (h0,h1,bb0,bb1) pixel-pair quads
    __shared__ float  s_min[2][2][256];  // per row, per point-half: min dist2
    __shared__ float  s_red[32], s_red2[32];
    __shared__ float  s_M;

    int tid  = threadIdx.x;              // 0..1023
    int row  = tid >> 9;                 // 0/1 within the row pair
    int t    = tid & 511;                // point index within row
    int y    = blockIdx.x * 2 + row;

    // ---- per-row point table (quad layout) + corner max (separable) --------
    float py = pts[2 * t], px = pts[2 * t + 1];
    float dx = (float)y - py;
    {
        float* prefs = (float*)pre4[row];
        int cell = t >> 1, par = t & 1;
        prefs[cell * 4 + par]     = -px;
        prefs[cell * 4 + 2 + par] = dx * dx;
    }
    float my = fmaxf(py, 255.0f - py);
    float mx = fmaxf(px, 255.0f - px);
    float lmax = fmaf(my, my, mx * mx);

    float h = 0.f;
    if (t < WW) {
        h = hm[y * WW + t];
        s_hm[row][t] = h;
    }

    int warp = tid >> 5, lane = tid & 31;
    for (int o = 16; o > 0; o >>= 1)
        lmax = fmaxf(lmax, __shfl_down_sync(0xffffffffu, lmax, o));
    if (lane == 0) s_red[warp] = lmax;
    __syncthreads();
    if (tid == 0) {
        float m = s_red[0];
#pragma unroll
        for (int i = 1; i < 32; ++i) m = fmaxf(m, s_red[i]);
        s_M = sqrtf(m);
    }
    __syncthreads();
    float M = s_M;

    // ---- build (h,h,bb,bb) pixel-pair quads (t < 128 per row) ---------------
    if (t < WW / 2) {
        float h0 = s_hm[row][2 * t], h1 = s_hm[row][2 * t + 1];
        s_hb[row][t] = make_float4(h0, h1, fmaf(-h0, M, M), fmaf(-h1, M, M));
    }
    __syncthreads();

    // ---------------- Phase A: per-pixel min dist2 (2 threads/pixel) --------
    {
        int p  = tid & 255;              // pixel
        int hp = (tid >> 8) & 1;         // which half of the points
        float xf = (float)p;
        ull XF2 = pk2(xf, xf);
        const float4* ptab = &pre4[row][hp * 128];
        float mins = 3.4e38f;
#pragma unroll 8
        for (int k = 0; k < 128; ++k) {
            float4 q = ptab[k];          // (-px0,-px1,dxs0,dxs1): aligned pairs
            ull NPX = pk2(q.x, q.y);
            ull DXS = pk2(q.z, q.w);
            ull DY  = f2add(XF2, NPX);
            ull S   = f2fma(DY, DY, DXS);
            float s0, s1; upk2(S, s0, s1);
            mins = fminf(mins, fminf(s0, s1));
        }
        s_min[row][hp][p] = mins;
    }
    __syncthreads();
    {
        int p  = tid & 255;
        int hp = (tid >> 8) & 1;
        float t1 = 0.f, ah = 0.f;
        if (hp == 0) {                   // these threads hold h for pixel p
            float mins = fminf(s_min[row][0][p], s_min[row][1][p]);
            t1 = h * sqrtf(mins);
            ah = fabsf(h);
        }
        for (int o = 16; o > 0; o >>= 1) {
            t1 += __shfl_down_sync(0xffffffffu, t1, o);
            ah += __shfl_down_sync(0xffffffffu, ah, o);
        }
        if (lane == 0) { s_red[warp] = t1; s_red2[warp] = ah; }
    }
    __syncthreads();
    if (t == 0) {                        // one finisher per row
        int w0 = row * 16;               // row's hp==0 warps
        float a = 0.f, b = 0.f;
#pragma unroll
        for (int i = 0; i < 8; ++i) { a += s_red[w0 + i]; b += s_red2[w0 + i]; }
        g_numA[y] = a;
        g_denA[y] = b;
    }

    // ---------------- Phase B: pixel-pair packed soft-min power sums ---------
    {
        const float* prefs = (const float*)pre4[row];
        int base = (t >> 1) * 4 + (t & 1);
        float np  = prefs[base];         // -px for point t
        float dxs = prefs[base + 2];     // (y-py)^2

        ull DY   = pk2(np, np + 1.0f);   // (x0-px, x1-px) at x=0
        ull DXS  = pk2(dxs, dxs);
        ull TWO2 = pk2(2.0f, 2.0f);
        ull ONE2 = pk2(1.0f, 1.0f);
        ull SACC = 0;
        const float4* hb = s_hb[row];

#pragma unroll 8
        for (int x = 0; x < WW / 2; ++x) {
            float4 q = hb[x];                 // (h0,h1,bb0,bb1) one LDS.128
            ull H2  = pk2(q.x, q.y);
            ull BB2 = pk2(q.z, q.w);
            ull S   = f2fma(DY, DY, DXS);
            float sA, sB; upk2(S, sA, sB);
            float rA = frsqrt_a(sA);
            float rB = frsqrt_a(sB);
            ull R  = pk2(rA, rB);
            ull D  = f2mul(S, R);             // sqrt(s)
            ull W  = f2fma(H2, D, BB2);       // w = h*d + (1-h)*M
            // packed Newton reciprocal: single 64-bit magic seed (no borrow
            // crossing: all positive float bits < 0x7EF311C3) + 2 iterations
            ull Y  = 0x7EF311C37EF311C3ULL - W;
            ull NW = W ^ 0x8000000080000000ULL;
            ull E;
            E = f2fma(NW, Y, ONE2); Y = f2fma(Y, E, Y);
            E = f2fma(NW, Y, ONE2); Y = f2fma(Y, E, Y);
            ull Q2 = f2mul(Y, Y);
            ull Q4 = f2mul(Q2, Q2);
            SACC = f2fma(Q4, Y, SACC);        // += w^-5
            DY = f2add(DY, TWO2);
        }
        float SA, SB; upk2(SACC, SA, SB);
        atomicAdd(&g_sum[t], SA + SB);        // one add per (row, point)
    }

    // ---------------- last-block epilogue ------------------------------------
    __shared__ int s_last;
    __threadfence();
    __syncthreads();
    if (tid == 0) s_last = (atomicAdd(&g_ctr, 1) == (int)gridDim.x - 1);
    __syncthreads();
    if (!s_last) return;

    float* red = (float*)pre4;           // reuse smem
    float* r2  = (float*)s_hm;
    float* r3  = (float*)s_min;
    if (tid < PP) {
        float Ssum = g_sum[tid];
        red[tid] = powf(Ssum * (1.0f / (HH * WW)), -0.2f);  // mean^(1/ALPHA)
        g_sum[tid] = 0.f;                // reset for next replay
    }
    if (tid < HH) { r2[tid] = g_numA[tid]; r3[tid] = g_denA[tid]; }
    __syncthreads();
    for (int o = 256; o > 0; o >>= 1) {
        if (tid < o) red[tid] += red[tid + o];
        __syncthreads();
    }
    for (int o = 128; o > 0; o >>= 1) {
        if (tid < o) { r2[tid] += r2[tid + o]; r3[tid] += r3[tid + o]; }
        __syncthreads();
    }
    if (tid == 0) {
        out[0] = r2[0] / r3[0] + red[0] * (1.0f / PP);
        g_ctr = 0;                       // reset for next replay
    }
}

extern "C" void kernel_launch(void* const* d_in, const int* in_sizes, int n_in,
                              void* d_out, int out_size) {
    (void)in_sizes; (void)n_in; (void)out_size;
    const float* hm  = (const float*)d_in[0];   // heat_map (256*256)
    const float* pts = (const float*)d_in[1];   // points   (512*2)
    float* out = (float*)d_out;

    k_all<<<HH / 2, 1024>>>(hm, pts, out);
}

// round 8
// speedup vs baseline: 1.6521x; 1.0570x over previous
#include <cuda_runtime.h>

#define HH 256
#define WW 256
#define PP 512
// ALPHA = -5.0f, 1/ALPHA = -0.2f

typedef unsigned long long ull;

__device__ float g_sum[PP];          // zero-init at load; reset by epilogue
__device__ float g_numA[HH];
__device__ float g_denA[HH];
__device__ int   g_ctr = 0;

__device__ __forceinline__ float frsqrt_a(float x) {
    float r; asm("rsqrt.approx.f32 %0, %1;" : "=f"(r) : "f"(x)); return r;
}
__device__ __forceinline__ ull pk2(float lo, float hi) {
    ull r; asm("mov.b64 %0, {%1, %2};" : "=l"(r) : "f"(lo), "f"(hi)); return r;
}
__device__ __forceinline__ void upk2(ull v, float& lo, float& hi) {
    asm("mov.b64 {%0, %1}, %2;" : "=f"(lo), "=f"(hi) : "l"(v));
}
__device__ __forceinline__ ull f2add(ull a, ull b) {
    ull r; asm("add.rn.f32x2 %0, %1, %2;" : "=l"(r) : "l"(a), "l"(b)); return r;
}
__device__ __forceinline__ ull f2mul(ull a, ull b) {
    ull r; asm("mul.rn.f32x2 %0, %1, %2;" : "=l"(r) : "l"(a), "l"(b)); return r;
}
__device__ __forceinline__ ull f2fma(ull a, ull b, ull c) {
    ull r; asm("fma.rn.f32x2 %0, %1, %2, %3;" : "=l"(r) : "l"(a), "l"(b), "l"(c)); return r;
}

// ---------------------------------------------------------------------------
// Single fused kernel: 128 blocks x 1024 threads (one wave, 8 warps/SMSP).
// __launch_bounds__(1024, 1): exactly one resident block -> ptxas may use
// 64 regs/thread, enabling real ILP across the unrolled Newton chains.
// Block b owns rows 2b, 2b+1. Phase B uses negated (h, bb) quads so the
// Newton seed needs no sign-flip XOR. Soft sums via atomicAdd(g_sum); the
// last block (fence + counter) finalizes and resets state.
// ---------------------------------------------------------------------------
__global__ __launch_bounds__(1024, 1) void k_all(const float* __restrict__ hm,
                                                 const float* __restrict__ pts,
                                                 float* __restrict__ out) {
    __shared__ float4 pre4[2][PP / 2];   // per row: (-px0,-px1,dxs0,dxs1) quads
    __shared__ float  s_hm[2][WW];       // per row: raw h
    __shared__ float4 s_hb[2][WW / 2];   // per row: (-h0,-h1,-bb0,-bb1) quads
    __shared__ float  s_min[2][2][256];  // per row, per point-half: min dist2
    __shared__ float  s_red[32], s_red2[32];
    __shared__ float  s_M;

    int tid  = threadIdx.x;              // 0..1023
    int row  = tid >> 9;                 // 0/1 within the row pair
    int t    = tid & 511;                // point index within row
    int y    = blockIdx.x * 2 + row;

    // ---- per-row point table (quad layout) + corner max (separable) --------
    float py = pts[2 * t], px = pts[2 * t + 1];
    float dx = (float)y - py;
    {
        float* prefs = (float*)pre4[row];
        int cell = t >> 1, par = t & 1;
        prefs[cell * 4 + par]     = -px;
        prefs[cell * 4 + 2 + par] = dx * dx;
    }
    float my = fmaxf(py, 255.0f - py);
    float mx = fmaxf(px, 255.0f - px);
    float lmax = fmaf(my, my, mx * mx);

    float h = 0.f;
    if (t < WW) {
        h = hm[y * WW + t];
        s_hm[row][t] = h;
    }

    int warp = tid >> 5, lane = tid & 31;
    for (int o = 16; o > 0; o >>= 1)
        lmax = fmaxf(lmax, __shfl_down_sync(0xffffffffu, lmax, o));
    if (lane == 0) s_red[warp] = lmax;
    __syncthreads();
    if (tid == 0) {
        float m = s_red[0];
#pragma unroll
        for (int i = 1; i < 32; ++i) m = fmaxf(m, s_red[i]);
        s_M = sqrtf(m);
    }
    __syncthreads();
    float M = s_M;

    // ---- build negated (h, bb) pixel-pair quads (t < 128 per row) -----------
    if (t < WW / 2) {
        float h0 = s_hm[row][2 * t], h1 = s_hm[row][2 * t + 1];
        // store (-h0, -h1, -(1-h0)M, -(1-h1)M)
        s_hb[row][t] = make_float4(-h0, -h1, fmaf(h0, M, -M), fmaf(h1, M, -M));
    }
    __syncthreads();

    // ---------------- Phase A: per-pixel min dist2 (2 threads/pixel) --------
    {
        int p  = tid & 255;              // pixel
        int hp = (tid >> 8) & 1;         // which half of the points
        float xf = (float)p;
        ull XF2 = pk2(xf, xf);
        const float4* ptab = &pre4[row][hp * 128];
        float mins = 3.4e38f;
#pragma unroll 8
        for (int k = 0; k < 128; ++k) {
            float4 q = ptab[k];          // (-px0,-px1,dxs0,dxs1): aligned pairs
            ull NPX = pk2(q.x, q.y);
            ull DXS = pk2(q.z, q.w);
            ull DY  = f2add(XF2, NPX);
            ull S   = f2fma(DY, DY, DXS);
            float s0, s1; upk2(S, s0, s1);
            mins = fminf(mins, fminf(s0, s1));
        }
        s_min[row][hp][p] = mins;
    }
    __syncthreads();
    {
        int p  = tid & 255;
        int hp = (tid >> 8) & 1;
        float t1 = 0.f, ah = 0.f;
        if (hp == 0) {                   // these threads hold h for pixel p
            float mins = fminf(s_min[row][0][p], s_min[row][1][p]);
            t1 = h * sqrtf(mins);
            ah = fabsf(h);
        }
        for (int o = 16; o > 0; o >>= 1) {
            t1 += __shfl_down_sync(0xffffffffu, t1, o);
            ah += __shfl_down_sync(0xffffffffu, ah, o);
        }
        if (lane == 0) { s_red[warp] = t1; s_red2[warp] = ah; }
    }
    __syncthreads();
    if (t == 0) {                        // one finisher per row
        int w0 = row * 16;               // row's hp==0 warps
        float a = 0.f, b = 0.f;
#pragma unroll
        for (int i = 0; i < 8; ++i) { a += s_red[w0 + i]; b += s_red2[w0 + i]; }
        g_numA[y] = a;
        g_denA[y] = b;
    }

    // ---------------- Phase B: pixel-pair packed soft-min power sums ---------
    {
        const float* prefs = (const float*)pre4[row];
        int base = (t >> 1) * 4 + (t & 1);
        float np  = prefs[base];         // -px for point t
        float dxs = prefs[base + 2];     // (y-py)^2

        ull DY   = pk2(np, np + 1.0f);   // (x0-px, x1-px) at x=0
        ull DXS  = pk2(dxs, dxs);
        ull TWO2 = pk2(2.0f, 2.0f);
        ull ONE2 = pk2(1.0f, 1.0f);
        ull SACC = 0;
        const float4* hb = s_hb[row];

#pragma unroll 8
        for (int x = 0; x < WW / 2; ++x) {
            float4 q = hb[x];                 // (-h0,-h1,-bb0,-bb1) one LDS.128
            ull NH2  = pk2(q.x, q.y);
            ull NBB2 = pk2(q.z, q.w);
            ull S    = f2fma(DY, DY, DXS);
            float sA, sB; upk2(S, sA, sB);
            float rA = frsqrt_a(sA);
            float rB = frsqrt_a(sB);
            ull R  = pk2(rA, rB);
            ull D  = f2mul(S, R);             // sqrt(s)
            ull NW = f2fma(NH2, D, NBB2);     // -w = -(h*d + (1-h)*M)
            // packed Newton reciprocal of w from NW: bits(-w)=bits(w)+sign,
            // so seed = (magic+0x80000000) - bits(-w), per-lane, no borrow.
            ull Y  = 0xFEF311C3FEF311C3ULL - NW;
            ull E;
            E = f2fma(NW, Y, ONE2); Y = f2fma(Y, E, Y);
            E = f2fma(NW, Y, ONE2); Y = f2fma(Y, E, Y);
            ull Q2 = f2mul(Y, Y);
            ull Q4 = f2mul(Q2, Q2);
            SACC = f2fma(Q4, Y, SACC);        // += w^-5
            DY = f2add(DY, TWO2);
        }
        float SA, SB; upk2(SACC, SA, SB);
        atomicAdd(&g_sum[t], SA + SB);        // one add per (row, point)
    }

    // ---------------- last-block epilogue ------------------------------------
    __shared__ int s_last;
    __threadfence();
    __syncthreads();
    if (tid == 0) s_last = (atomicAdd(&g_ctr, 1) == (int)gridDim.x - 1);
    __syncthreads();
    if (!s_last) return;

    float* red = (float*)pre4;           // reuse smem
    float* r2  = (float*)s_hm;
    float* r3  = (float*)s_min;
    if (tid < PP) {
        float Ssum = g_sum[tid];
        red[tid] = powf(Ssum * (1.0f / (HH * WW)), -0.2f);  // mean^(1/ALPHA)
        g_sum[tid] = 0.f;                // reset for next replay
    }
    if (tid < HH) { r2[tid] = g_numA[tid]; r3[tid] = g_denA[tid]; }
    __syncthreads();
    for (int o = 256; o > 0; o >>= 1) {
        if (tid < o) red[tid] += red[tid + o];
        __syncthreads();
    }
    for (int o = 128; o > 0; o >>= 1) {
        if (tid < o) { r2[tid] += r2[tid + o]; r3[tid] += r3[tid + o]; }
        __syncthreads();
    }
    if (tid == 0) {
        out[0] = r2[0] / r3[0] + red[0] * (1.0f / PP);
        g_ctr = 0;                       // reset for next replay
    }
}

extern "C" void kernel_launch(void* const* d_in, const int* in_sizes, int n_in,
                              void* d_out, int out_size) {
    (void)in_sizes; (void)n_in; (void)out_size;
    const float* hm  = (const float*)d_in[0];   // heat_map (256*256)
    const float* pts = (const float*)d_in[1];   // points   (512*2)
    float* out = (float*)d_out;

    k_all<<<HH / 2, 1024>>>(hm, pts, out);
}